// round 8
// baseline (speedup 1.0000x reference)
#include <cuda_runtime.h>
#include <cuda_bf16.h>
#include <stdint.h>

#define B_   8
#define C_   64
#define NV   40962
#define K_   7
#define CK   448
#define VT   128            // vertices per main CTA (2 CTAs/SM)

// ---------------------------------------------------------------------------
// Static device scratch (no runtime allocation allowed)
// ---------------------------------------------------------------------------
__device__ __align__(256) float g_xt[(size_t)B_ * NV * C_];  // [b][n][c], tf32-rounded fp32
__device__ __align__(256) unsigned char g_wt[K_ * 16384];    // [k] 64x64 f32 tile, SW128 half-rows

// ---------------------------------------------------------------------------
// PTX helpers (baseline-sm_100-legal: cp.async, ldmatrix, mma.sync tf32)
// ---------------------------------------------------------------------------
__device__ __forceinline__ uint32_t smem_u32(const void* p) {
    uint32_t a;
    asm("{ .reg .u64 t; cvta.to.shared.u64 t, %1; cvt.u32.u64 %0, t; }" : "=r"(a) : "l"(p));
    return a;
}
__device__ __forceinline__ uint32_t f2tf32(float v) {
    uint32_t u;
    asm("cvt.rna.tf32.f32 %0, %1;" : "=r"(u) : "f"(v));
    return u;
}
#define CP16(dst, src) \
    asm volatile("cp.async.cg.shared.global [%0], [%1], 16;" :: "r"(dst), "l"(src) : "memory")
#define CP_COMMIT() asm volatile("cp.async.commit_group;" ::: "memory")
#define CP_WAIT1()  asm volatile("cp.async.wait_group 1;" ::: "memory")
#define CP_WAIT0()  asm volatile("cp.async.wait_group 0;" ::: "memory")

#define LDM_X4(r0, r1, r2, r3, a) \
    asm volatile("ldmatrix.sync.aligned.m8n8.x4.shared.b16 {%0,%1,%2,%3}, [%4];" \
                 : "=r"(r0), "=r"(r1), "=r"(r2), "=r"(r3) : "r"(a))

#define MMA16808TF(d, a, b) \
    asm volatile("mma.sync.aligned.m16n8k8.row.col.f32.tf32.tf32.f32 " \
                 "{%0,%1,%2,%3}, {%4,%5,%6,%7}, {%8,%9}, {%0,%1,%2,%3};" \
                 : "+f"((d)[0]), "+f"((d)[1]), "+f"((d)[2]), "+f"((d)[3]) \
                 : "r"((a)[0]), "r"((a)[1]), "r"((a)[2]), "r"((a)[3]), \
                   "r"((b)[0]), "r"((b)[1]))

#define SWZ(o) ((o) ^ (((o) >> 3) & 0x70))

// ---------------------------------------------------------------------------
// SMEM layout (bytes): stage = A 32K (128v x 256B as swizzled 128B half-rows)
//                              | W 16K (64o x 256B likewise) = 48K, x2 stages
// ---------------------------------------------------------------------------
#define SOFF_A(p)    ((p) * 49152)
#define SOFF_W(p)    ((p) * 49152 + 32768)
#define SOFF_NEIGH   98304                   // VT*K_*4 = 3584
#define SOFF_BIAS    101888                  // 256
#define SMEM_TOTAL   102144                  // 2 CTAs/SM

// ---------------------------------------------------------------------------
// Kernel 1: transpose x [B,C,N] -> g_xt [B,N,C] fp32 rounded to tf32 (RN)
// ---------------------------------------------------------------------------
__global__ void xprep_kernel(const float* __restrict__ x) {
    __shared__ float tile[32][33];
    const int b  = blockIdx.z;
    const int c0 = blockIdx.y * 32;
    const int n0 = blockIdx.x * 32;
    const int tx = threadIdx.x, ty = threadIdx.y;

    #pragma unroll
    for (int s = 0; s < 4; s++) {
        const int c = c0 + ty + s * 8;
        const int n = n0 + tx;
        float v = 0.0f;
        if (n < NV) v = x[((size_t)b * C_ + c) * NV + n];
        tile[ty + s * 8][tx] = v;
    }
    __syncthreads();
    #pragma unroll
    for (int s = 0; s < 4; s++) {
        const int n = n0 + ty + s * 8;
        const int c = c0 + tx;
        if (n < NV) {
            const uint32_t t32 = f2tf32(tile[tx][ty + s * 8]);
            ((uint32_t*)g_xt)[((size_t)b * NV + n) * C_ + c] = t32;
        }
    }
}

// ---------------------------------------------------------------------------
// Kernel 2: W [o][c*7+k] -> g_wt [k] 64x64 tf32-rounded f32 tile:
//           byte = ((o*2 + c/32)*128 + (c%32)*4), SW128-swizzled
// ---------------------------------------------------------------------------
__global__ void wprep_kernel(const float* __restrict__ W) {
    const int e = blockIdx.x * 256 + threadIdx.x;   // over 7*64*64
    if (e >= K_ * C_ * C_) return;
    const int c = e & 63;
    const int o = (e >> 6) & 63;
    const int k = e >> 12;
    const uint32_t t32 = f2tf32(W[o * CK + c * K_ + k]);
    const uint32_t byte = (uint32_t)((o * 2 + (c >> 5)) * 128 + (c & 31) * 4);
    *(uint32_t*)(g_wt + (size_t)k * 16384 + SWZ(byte)) = t32;
}

// ---------------------------------------------------------------------------
// Kernel 3: gather + tf32 mma.sync. 1 CTA = (batch, 128 vertices).
// 256 threads / 8 warps; warp = 32 vertices x 32 outputs; 2 CTAs/SM.
// ---------------------------------------------------------------------------
extern __shared__ char smem_raw[];

__device__ __forceinline__ void stage_load(
    int p, int k, int vmax, const int* sN,
    const float* xtb, uint32_t sb, int tid)
{
    // A: 128 rows x 256B. thread t -> row t>>1, half t&1 (128B each)
    const int v  = tid >> 1;
    const int hf = tid & 1;
    const int j  = (v < vmax) ? sN[v * K_ + k] : 0;
    const char* src = (const char*)(xtb + (size_t)j * C_ + hf * 32);
    const uint32_t aBase = sb + SOFF_A(p);
    const uint32_t hrow  = (uint32_t)((v * 2 + hf) * 128);
    #pragma unroll
    for (int t = 0; t < 8; t++) {
        CP16(aBase + SWZ(hrow + t * 16), src + t * 16);
    }
    // W: 16KB pre-swizzled, linear copy: 1024 CP16 over 256 threads
    const char* wsrc = (const char*)g_wt + (size_t)k * 16384;
    const uint32_t wdst = sb + SOFF_W(p);
    #pragma unroll
    for (int i = 0; i < 4; i++) {
        const int idx = tid + i * 256;
        CP16(wdst + (uint32_t)idx * 16, wsrc + (size_t)idx * 16);
    }
}

__global__ __launch_bounds__(256, 2)
void iconv_mma_kernel(const int* __restrict__ neigh,
                      const float* __restrict__ bias,
                      float* __restrict__ out) {
    const uint32_t sb = smem_u32(smem_raw);
    const int tid  = threadIdx.x;
    const int lane = tid & 31;
    const int wid  = tid >> 5;
    const int b    = blockIdx.y;
    const int n0   = blockIdx.x * VT;
    const int vmax = min(VT, NV - n0);

    // stage bias + neighbor indices
    if (tid < C_) ((float*)(smem_raw + SOFF_BIAS))[tid] = bias[tid];
    {
        int* sN = (int*)(smem_raw + SOFF_NEIGH);
        const int lim = vmax * K_;
        #pragma unroll
        for (int i = 0; i < 4; i++) {
            const int q = tid + i * 256;
            if (q < VT * K_) sN[q] = (q < lim) ? neigh[(size_t)n0 * K_ + q] : 0;
        }
    }
    __syncthreads();

    const int* sN = (const int*)(smem_raw + SOFF_NEIGH);
    const float* xtb = g_xt + (size_t)b * NV * C_;

    // warp tiling: 4 v-groups x 2 o-groups
    const int vg = wid >> 1;                  // vertices [vg*32, +32)
    const int og = wid & 1;                   // outputs  [og*32, +32)

    // per-lane ldmatrix address components (tf32 fragments via b16 ldmatrix)
    const int lg = lane >> 3;                 // matrix group 0..3
    const int lr = lane & 7;                  // row within group
    // A: m0 v0-7 seg0, m1 v8-15 seg0, m2 v0-7 seg1, m3 v8-15 seg1
    const int aVoff  = ((lg & 1) << 3) + lr;  // + vbase
    const int aSeg   = lg >> 1;               // float offset 0 or 4
    // B: m0 o0-7 seg0, m1 o0-7 seg1, m2 o8-15 seg0, m3 o8-15 seg1
    const int bOoff  = ((lg >> 1) << 3) + lr; // + obase
    const int bSeg   = lg & 1;

    float acc[2][4][4];
    #pragma unroll
    for (int i = 0; i < 2; i++)
        #pragma unroll
        for (int j = 0; j < 4; j++)
            #pragma unroll
            for (int r = 0; r < 4; r++) acc[i][j][r] = 0.0f;

    stage_load(0, 0, vmax, sN, xtb, sb, tid);
    CP_COMMIT();

    for (int k = 0; k < K_; k++) {
        const int p = k & 1;
        if (k < K_ - 1) {
            stage_load(p ^ 1, k + 1, vmax, sN, xtb, sb, tid);
            CP_COMMIT();
            CP_WAIT1();
        } else {
            CP_WAIT0();
        }
        __syncthreads();

        const uint32_t aB = sb + SOFF_A(p);
        const uint32_t wB = sb + SOFF_W(p);

        #pragma unroll
        for (int kk = 0; kk < 8; kk++) {           // k8 chunks over 64 floats
            const int c0  = kk * 8;
            const int h   = c0 >> 5;               // which 128B half-row
            const int c0p = c0 & 31;

            uint32_t aF[2][4];
            #pragma unroll
            for (int i = 0; i < 2; i++) {
                const int vrow = vg * 32 + i * 16 + aVoff;
                const uint32_t byte =
                    (uint32_t)((vrow * 2 + h) * 128 + (c0p + aSeg * 4) * 4);
                LDM_X4(aF[i][0], aF[i][1], aF[i][2], aF[i][3], aB + SWZ(byte));
            }
            uint32_t bF[4][2];
            #pragma unroll
            for (int jo = 0; jo < 2; jo++) {       // o-blocks of 16
                const int orow = og * 32 + jo * 16 + bOoff;
                const uint32_t byte =
                    (uint32_t)((orow * 2 + h) * 128 + (c0p + bSeg * 4) * 4);
                uint32_t r0, r1, r2, r3;
                LDM_X4(r0, r1, r2, r3, wB + SWZ(byte));
                bF[2 * jo][0]     = r0;  bF[2 * jo][1]     = r1;  // o8 group lo
                bF[2 * jo + 1][0] = r2;  bF[2 * jo + 1][1] = r3;  // o8 group hi
            }
            #pragma unroll
            for (int i = 0; i < 2; i++)
                #pragma unroll
                for (int j = 0; j < 4; j++)
                    MMA16808TF(acc[i][j], aF[i], bF[j]);
        }
        __syncthreads();   // done reading buf p before it is overwritten
    }

    // ---- epilogue: regs -> smem stage [v*65 + o] -> coalesced stores ----
    {
        float* st = (float*)smem_raw;      // 128*65*4 = 33,280 B (reuses stage 0)
        const int gid = lane >> 2;
        const int tg  = lane & 3;
        #pragma unroll
        for (int i = 0; i < 2; i++)
            #pragma unroll
            for (int j = 0; j < 4; j++)
                #pragma unroll
                for (int r = 0; r < 4; r++) {
                    const int v = vg * 32 + i * 16 + gid + (r >> 1) * 8;
                    const int o = og * 32 + j * 8 + 2 * tg + (r & 1);
                    st[v * 65 + o] = acc[i][j][r];
                }
        __syncthreads();

        const float* sBias = (const float*)(smem_raw + SOFF_BIAS);
        const int v  = tid & 127;          // 128 consecutive v -> full coalescing
        const int oh = (tid >> 7) * 32;    // output half
        if (v < vmax) {
            #pragma unroll
            for (int oo = 0; oo < 32; oo++) {
                const int o = oh + oo;
                out[((size_t)b * C_ + o) * NV + n0 + v] = st[v * 65 + o] + sBias[o];
            }
        }
    }
}

// ---------------------------------------------------------------------------
// Launch
// ---------------------------------------------------------------------------
extern "C" void kernel_launch(void* const* d_in, const int* in_sizes, int n_in,
                              void* d_out, int out_size) {
    const float* x     = (const float*)d_in[0];
    const int*   neigh = (const int*)d_in[1];    // JAX x64 disabled -> int32
    const float* W     = (const float*)d_in[2];
    const float* bias  = (const float*)d_in[3];
    float*       out   = (float*)d_out;

    cudaFuncSetAttribute(iconv_mma_kernel,
                         cudaFuncAttributeMaxDynamicSharedMemorySize, SMEM_TOTAL);

    dim3 tgrid((NV + 31) / 32, C_ / 32, B_);
    xprep_kernel<<<tgrid, dim3(32, 8)>>>(x);

    wprep_kernel<<<(K_ * C_ * C_ + 255) / 256, 256>>>(W);

    dim3 mgrid((NV + VT - 1) / VT, B_);          // (321, 8)
    iconv_mma_kernel<<<mgrid, 256, SMEM_TOTAL>>>(neigh, bias, out);
}

// round 9
// speedup vs baseline: 1.5540x; 1.5540x over previous
#include <cuda_runtime.h>
#include <cuda_bf16.h>
#include <stdint.h>

#define B_   8
#define C_   64
#define NV   40962
#define K_   7
#define CK   448
#define VT   128            // vertices per main CTA (2 CTAs/SM)

// ---------------------------------------------------------------------------
// Static device scratch (no runtime allocation allowed)
// ---------------------------------------------------------------------------
__device__ __align__(256) __nv_bfloat16 g_xhi[(size_t)B_ * NV * C_];  // [b][n][c] hi
__device__ __align__(256) __nv_bfloat16 g_xlo[(size_t)B_ * NV * C_];  // [b][n][c] lo
__device__ __align__(256) unsigned char g_wsw[K_ * 16384];            // [k][hi 8KB | lo 8KB], SW128

// ---------------------------------------------------------------------------
// PTX helpers (baseline-sm_100-legal: cp.async, ldmatrix, mma.sync)
// ---------------------------------------------------------------------------
__device__ __forceinline__ uint32_t smem_u32(const void* p) {
    uint32_t a;
    asm("{ .reg .u64 t; cvta.to.shared.u64 t, %1; cvt.u32.u64 %0, t; }" : "=r"(a) : "l"(p));
    return a;
}
#define CP16(dst, src) \
    asm volatile("cp.async.cg.shared.global [%0], [%1], 16;" :: "r"(dst), "l"(src) : "memory")
#define CP_COMMIT() asm volatile("cp.async.commit_group;" ::: "memory")
#define CP_WAIT1()  asm volatile("cp.async.wait_group 1;" ::: "memory")
#define CP_WAIT0()  asm volatile("cp.async.wait_group 0;" ::: "memory")

#define LDM_X4(r0, r1, r2, r3, a) \
    asm volatile("ldmatrix.sync.aligned.m8n8.x4.shared.b16 {%0,%1,%2,%3}, [%4];" \
                 : "=r"(r0), "=r"(r1), "=r"(r2), "=r"(r3) : "r"(a))

#define MMA16816(d, a, b) \
    asm volatile("mma.sync.aligned.m16n8k16.row.col.f32.bf16.bf16.f32 " \
                 "{%0,%1,%2,%3}, {%4,%5,%6,%7}, {%8,%9}, {%0,%1,%2,%3};" \
                 : "+f"((d)[0]), "+f"((d)[1]), "+f"((d)[2]), "+f"((d)[3]) \
                 : "r"((a)[0]), "r"((a)[1]), "r"((a)[2]), "r"((a)[3]), \
                   "r"((b)[0]), "r"((b)[1]))

#define SWZ(o) ((o) ^ (((o) >> 3) & 0x70))

// ---------------------------------------------------------------------------
// SMEM layout (bytes): stage = AHI 16K | ALO 16K | W 16K = 48K, x2 stages
// ---------------------------------------------------------------------------
#define SOFF_AHI(p)  ((p) * 49152)
#define SOFF_ALO(p)  ((p) * 49152 + 16384)
#define SOFF_W(p)    ((p) * 49152 + 32768)
#define SOFF_NEIGH   98304                   // VT*K_*4 = 3584
#define SOFF_BIAS    101888                  // 256
#define SMEM_TOTAL   102144                  // 2 CTAs/SM: 204.3KB

// ---------------------------------------------------------------------------
// Kernel 1: split-transpose x [B,C,N] -> xt_hi/xt_lo [B,N,C] bf16
// ---------------------------------------------------------------------------
__global__ void xsplit_kernel(const float* __restrict__ x) {
    __shared__ float tile[32][33];
    const int b  = blockIdx.z;
    const int c0 = blockIdx.y * 32;
    const int n0 = blockIdx.x * 32;
    const int tx = threadIdx.x, ty = threadIdx.y;

    #pragma unroll
    for (int s = 0; s < 4; s++) {
        const int c = c0 + ty + s * 8;
        const int n = n0 + tx;
        float v = 0.0f;
        if (n < NV) v = x[((size_t)b * C_ + c) * NV + n];
        tile[ty + s * 8][tx] = v;
    }
    __syncthreads();
    #pragma unroll
    for (int s = 0; s < 4; s++) {
        const int n = n0 + ty + s * 8;
        const int c = c0 + tx;
        if (n < NV) {
            const float v = tile[tx][ty + s * 8];
            const __nv_bfloat16 h = __float2bfloat16(v);
            const __nv_bfloat16 l = __float2bfloat16(v - __bfloat162float(h));
            const size_t o = ((size_t)b * NV + n) * C_ + c;
            g_xhi[o] = h;
            g_xlo[o] = l;
        }
    }
}

// ---------------------------------------------------------------------------
// Kernel 2: W [o][c*7+k] -> SW128-swizzled bf16 tiles [k][hi/lo][o rows 128B]
// ---------------------------------------------------------------------------
__global__ void wprep_kernel(const float* __restrict__ W) {
    const int e = blockIdx.x * 256 + threadIdx.x;   // over 7*64*64
    if (e >= K_ * C_ * C_) return;
    const int c = e & 63;
    const int o = (e >> 6) & 63;
    const int k = e >> 12;
    const float v = W[o * CK + c * K_ + k];
    const __nv_bfloat16 h = __float2bfloat16(v);
    const __nv_bfloat16 l = __float2bfloat16(v - __bfloat162float(h));
    const uint32_t sw = SWZ((uint32_t)(o * 128 + c * 2));
    *(__nv_bfloat16*)(g_wsw + (size_t)k * 16384 + sw)        = h;
    *(__nv_bfloat16*)(g_wsw + (size_t)k * 16384 + 8192 + sw) = l;
}

// ---------------------------------------------------------------------------
// Kernel 3: gather + mma.sync main kernel. 1 CTA = (batch, 128 vertices).
// 256 threads / 8 warps; warp = 32 vertices x 32 outputs; 2 CTAs per SM.
// ---------------------------------------------------------------------------
extern __shared__ char smem_raw[];

// Coalesced gather: each warp instruction covers 4 half-rows, 8 lanes x 16B
// contiguous per half-row -> 4 distinct 128B lines per instruction (vs 32
// in the per-lane-per-row layout). This is the L1tex wavefront minimum.
__device__ __forceinline__ void stage_load(
    int p, int k, int vmax, const int* sN,
    const __nv_bfloat16* xhb, const __nv_bfloat16* xlb,
    uint32_t sb, int tid)
{
    const int w   = tid >> 5;          // warp 0..7
    const int sub = (tid & 31) >> 3;   // half-row within instr 0..3
    const int ch  = tid & 7;           // 16B chunk 0..7
    #pragma unroll
    for (int i = 0; i < 8; i++) {
        const int hr   = i * 32 + w * 4 + sub;   // 0..255
        const int part = hr >> 7;                // 0 = hi, 1 = lo
        const int v    = hr & 127;
        const int j    = (v < vmax) ? sN[v * K_ + k] : 0;
        const char* src = (const char*)((part ? xlb : xhb) + (size_t)j * C_) + ch * 16;
        const uint32_t dst =
            sb + (part ? SOFF_ALO(p) : SOFF_AHI(p)) + SWZ((uint32_t)(v * 128 + ch * 16));
        CP16(dst, src);
    }
    // W: 16KB pre-swizzled, linear coalesced copy: 1024 CP16 over 256 threads
    const char* wsrc = (const char*)g_wsw + (size_t)k * 16384;
    const uint32_t wdst = sb + SOFF_W(p);
    #pragma unroll
    for (int i = 0; i < 4; i++) {
        const int idx = tid + i * 256;
        CP16(wdst + (uint32_t)idx * 16, wsrc + (size_t)idx * 16);
    }
}

__global__ __launch_bounds__(256, 2)
void iconv_mma_kernel(const int* __restrict__ neigh,
                      const float* __restrict__ bias,
                      float* __restrict__ out) {
    const uint32_t sb = smem_u32(smem_raw);
    const int tid  = threadIdx.x;
    const int lane = tid & 31;
    const int wid  = tid >> 5;
    const int b    = blockIdx.y;
    const int n0   = blockIdx.x * VT;
    const int vmax = min(VT, NV - n0);

    // stage bias + neighbor indices
    if (tid < C_) ((float*)(smem_raw + SOFF_BIAS))[tid] = bias[tid];
    {
        int* sN = (int*)(smem_raw + SOFF_NEIGH);
        const int lim = vmax * K_;
        #pragma unroll
        for (int i = 0; i < 4; i++) {
            const int q = tid + i * 256;
            if (q < VT * K_) sN[q] = (q < lim) ? neigh[(size_t)n0 * K_ + q] : 0;
        }
    }
    __syncthreads();

    const int* sN = (const int*)(smem_raw + SOFF_NEIGH);
    const __nv_bfloat16* xhb = g_xhi + (size_t)b * NV * C_;
    const __nv_bfloat16* xlb = g_xlo + (size_t)b * NV * C_;

    // warp tiling: 4 v-groups x 2 o-groups
    const int vg = wid >> 1;                  // 0..3 -> vertices [vg*32, +32)
    const int og = wid & 1;                   // 0..1 -> outputs  [og*32, +32)

    const int rowA = vg * 32 + (lane & 15);               // + i*16
    const uint32_t halfA = (uint32_t)((lane >> 4) * 16);
    const int rowB = (lane & 7) + ((lane >> 4) << 3);     // + og*32 + jp*16
    const uint32_t halfB = (uint32_t)(((lane >> 3) & 1) * 16);

    float acc[2][4][4];
    #pragma unroll
    for (int i = 0; i < 2; i++)
        #pragma unroll
        for (int j = 0; j < 4; j++)
            #pragma unroll
            for (int r = 0; r < 4; r++) acc[i][j][r] = 0.0f;

    stage_load(0, 0, vmax, sN, xhb, xlb, sb, tid);
    CP_COMMIT();

    for (int k = 0; k < K_; k++) {
        const int p = k & 1;
        if (k < K_ - 1) {
            stage_load(p ^ 1, k + 1, vmax, sN, xhb, xlb, sb, tid);
            CP_COMMIT();
            CP_WAIT1();
        } else {
            CP_WAIT0();
        }
        __syncthreads();

        const uint32_t aH = sb + SOFF_AHI(p);
        const uint32_t aL = sb + SOFF_ALO(p);
        const uint32_t wH = sb + SOFF_W(p);
        const uint32_t wL = wH + 8192;

        #pragma unroll
        for (int kk = 0; kk < 4; kk++) {
            uint32_t aHf[2][4], aLf[2][4];
            #pragma unroll
            for (int i = 0; i < 2; i++) {
                // half-offset added BEFORE the swizzle (no-carry there)
                const uint32_t offA =
                    SWZ((uint32_t)((rowA + i * 16) * 128 + kk * 32) + halfA);
                LDM_X4(aHf[i][0], aHf[i][1], aHf[i][2], aHf[i][3], aH + offA);
                LDM_X4(aLf[i][0], aLf[i][1], aLf[i][2], aLf[i][3], aL + offA);
            }
            uint32_t bHf[4][2], bLf[4][2];
            #pragma unroll
            for (int jp = 0; jp < 2; jp++) {
                const uint32_t offB =
                    SWZ((uint32_t)((og * 32 + jp * 16 + rowB) * 128 + kk * 32) + halfB);
                LDM_X4(bHf[2 * jp][0], bHf[2 * jp][1],
                       bHf[2 * jp + 1][0], bHf[2 * jp + 1][1], wH + offB);
                LDM_X4(bLf[2 * jp][0], bLf[2 * jp][1],
                       bLf[2 * jp + 1][0], bLf[2 * jp + 1][1], wL + offB);
            }
            #pragma unroll
            for (int i = 0; i < 2; i++)
                #pragma unroll
                for (int j = 0; j < 4; j++) {
                    MMA16816(acc[i][j], aHf[i], bHf[j]);   // hi*hi
                    MMA16816(acc[i][j], aHf[i], bLf[j]);   // hi*lo
                    MMA16816(acc[i][j], aLf[i], bHf[j]);   // lo*hi
                }
        }
        __syncthreads();   // done reading buf p before it is overwritten
    }

    // ---- epilogue: regs -> smem stage [v*65 + o] -> coalesced stores ----
    {
        float* st = (float*)smem_raw;      // 128*65*4 = 33,280 B (reuses stage 0)
        const int gid = lane >> 2;
        const int tg  = lane & 3;
        #pragma unroll
        for (int i = 0; i < 2; i++)
            #pragma unroll
            for (int j = 0; j < 4; j++)
                #pragma unroll
                for (int r = 0; r < 4; r++) {
                    const int v = vg * 32 + i * 16 + gid + (r >> 1) * 8;
                    const int o = og * 32 + j * 8 + 2 * tg + (r & 1);
                    st[v * 65 + o] = acc[i][j][r];
                }
        __syncthreads();

        const float* sBias = (const float*)(smem_raw + SOFF_BIAS);
        const int v  = tid & 127;          // 128 consecutive v -> full coalescing
        const int oh = (tid >> 7) * 32;    // output half
        if (v < vmax) {
            #pragma unroll
            for (int oo = 0; oo < 32; oo++) {
                const int o = oh + oo;
                out[((size_t)b * C_ + o) * NV + n0 + v] = st[v * 65 + o] + sBias[o];
            }
        }
    }
}

// ---------------------------------------------------------------------------
// Launch
// ---------------------------------------------------------------------------
extern "C" void kernel_launch(void* const* d_in, const int* in_sizes, int n_in,
                              void* d_out, int out_size) {
    const float* x     = (const float*)d_in[0];
    const int*   neigh = (const int*)d_in[1];    // JAX x64 disabled -> int32
    const float* W     = (const float*)d_in[2];
    const float* bias  = (const float*)d_in[3];
    float*       out   = (float*)d_out;

    cudaFuncSetAttribute(iconv_mma_kernel,
                         cudaFuncAttributeMaxDynamicSharedMemorySize, SMEM_TOTAL);

    dim3 tgrid((NV + 31) / 32, C_ / 32, B_);
    xsplit_kernel<<<tgrid, dim3(32, 8)>>>(x);

    wprep_kernel<<<(K_ * C_ * C_ + 255) / 256, 256>>>(W);

    dim3 mgrid((NV + VT - 1) / VT, B_);          // (321, 8)
    iconv_mma_kernel<<<mgrid, 256, SMEM_TOTAL>>>(neigh, bias, out);
}

// round 11
// speedup vs baseline: 2.7635x; 1.7783x over previous
#include <cuda_runtime.h>
#include <cuda_fp16.h>
#include <stdint.h>

#define B_   8
#define C_   64
#define NV   40962
#define K_   7
#define CK   448
#define VT   128            // vertices per main CTA

// ---------------------------------------------------------------------------
// Static device scratch (no runtime allocation allowed)
// ---------------------------------------------------------------------------
__device__ __align__(256) __half g_xh[(size_t)B_ * NV * C_];   // [b][n][c] fp16, 42 MB
__device__ __align__(256) unsigned char g_wf[K_ * 8192];       // [k] 64x64 fp16 tile, SW128

// ---------------------------------------------------------------------------
// PTX helpers (baseline-sm_100-legal: cp.async, ldmatrix, mma.sync fp16)
// ---------------------------------------------------------------------------
__device__ __forceinline__ uint32_t smem_u32(const void* p) {
    uint32_t a;
    asm("{ .reg .u64 t; cvta.to.shared.u64 t, %1; cvt.u32.u64 %0, t; }" : "=r"(a) : "l"(p));
    return a;
}
#define CP16(dst, src) \
    asm volatile("cp.async.cg.shared.global [%0], [%1], 16;" :: "r"(dst), "l"(src) : "memory")
#define CP_COMMIT() asm volatile("cp.async.commit_group;" ::: "memory")
#define CP_WAIT1()  asm volatile("cp.async.wait_group 1;" ::: "memory")
#define CP_WAIT0()  asm volatile("cp.async.wait_group 0;" ::: "memory")

#define LDM_X4(r0, r1, r2, r3, a) \
    asm volatile("ldmatrix.sync.aligned.m8n8.x4.shared.b16 {%0,%1,%2,%3}, [%4];" \
                 : "=r"(r0), "=r"(r1), "=r"(r2), "=r"(r3) : "r"(a))

#define MMA16816F(d, a, b) \
    asm volatile("mma.sync.aligned.m16n8k16.row.col.f32.f16.f16.f32 " \
                 "{%0,%1,%2,%3}, {%4,%5,%6,%7}, {%8,%9}, {%0,%1,%2,%3};" \
                 : "+f"((d)[0]), "+f"((d)[1]), "+f"((d)[2]), "+f"((d)[3]) \
                 : "r"((a)[0]), "r"((a)[1]), "r"((a)[2]), "r"((a)[3]), \
                   "r"((b)[0]), "r"((b)[1]))

#define SWZ(o) ((o) ^ (((o) >> 3) & 0x70))

// ---------------------------------------------------------------------------
// SMEM layout (bytes): stage = A 16K (128v x 128B swizzled) | W 8K = 24K, x2
// ---------------------------------------------------------------------------
#define SOFF_A(p)    ((p) * 24576)
#define SOFF_W(p)    ((p) * 24576 + 16384)
#define SOFF_NEIGH   49152                   // VT*K_*4 = 3584
#define SOFF_BIAS    52736                   // 256
#define SMEM_TOTAL   52992                   // 3 CTAs/SM: 158.9KB

// ---------------------------------------------------------------------------
// Kernel 1: transpose x [B,C,N] -> g_xh [B,N,C] fp16 (RN)
// ---------------------------------------------------------------------------
__global__ void xprep_kernel(const float* __restrict__ x) {
    __shared__ float tile[32][33];
    const int b  = blockIdx.z;
    const int c0 = blockIdx.y * 32;
    const int n0 = blockIdx.x * 32;
    const int tx = threadIdx.x, ty = threadIdx.y;

    #pragma unroll
    for (int s = 0; s < 4; s++) {
        const int c = c0 + ty + s * 8;
        const int n = n0 + tx;
        float v = 0.0f;
        if (n < NV) v = x[((size_t)b * C_ + c) * NV + n];
        tile[ty + s * 8][tx] = v;
    }
    __syncthreads();
    #pragma unroll
    for (int s = 0; s < 4; s++) {
        const int n = n0 + ty + s * 8;
        const int c = c0 + tx;
        if (n < NV)
            g_xh[((size_t)b * NV + n) * C_ + c] = __float2half_rn(tile[tx][ty + s * 8]);
    }
}

// ---------------------------------------------------------------------------
// Kernel 2: W [o][c*7+k] -> g_wf [k] 64x64 fp16 K-major tile, SW128 rows
// ---------------------------------------------------------------------------
__global__ void wprep_kernel(const float* __restrict__ W) {
    const int e = blockIdx.x * 256 + threadIdx.x;   // over 7*64*64
    if (e >= K_ * C_ * C_) return;
    const int c = e & 63;
    const int o = (e >> 6) & 63;
    const int k = e >> 12;
    const __half h = __float2half_rn(W[o * CK + c * K_ + k]);
    const uint32_t sw = SWZ((uint32_t)(o * 128 + c * 2));
    *(__half*)(g_wf + (size_t)k * 8192 + sw) = h;
}

// ---------------------------------------------------------------------------
// Kernel 3: gather + fp16 mma.sync. 1 CTA = (batch, 128 vertices).
// 256 threads / 8 warps; warp = 32 vertices x 32 outputs; 3 CTAs/SM.
// ---------------------------------------------------------------------------
extern __shared__ char smem_raw[];

// Coalesced gather: each warp instruction covers 4 rows, 8 lanes x 16B
// contiguous per row -> 4 distinct 128B lines per instruction (line minimum).
__device__ __forceinline__ void stage_load(
    int p, int k, int vmax, const int* sN,
    const __half* xhb, uint32_t sb, int tid)
{
    const int w   = tid >> 5;          // warp 0..7
    const int sub = (tid & 31) >> 3;   // row within instr 0..3
    const int ch  = tid & 7;           // 16B chunk 0..7
    #pragma unroll
    for (int i = 0; i < 4; i++) {
        const int v = i * 32 + w * 4 + sub;      // 0..127
        const int j = (v < vmax) ? sN[v * K_ + k] : 0;
        const char* src = (const char*)(xhb + (size_t)j * C_) + ch * 16;
        CP16(sb + SOFF_A(p) + SWZ((uint32_t)(v * 128 + ch * 16)), src);
    }
    // W: 8KB pre-swizzled, linear coalesced copy: 512 CP16 over 256 threads
    const char* wsrc = (const char*)g_wf + (size_t)k * 8192;
    const uint32_t wdst = sb + SOFF_W(p);
    #pragma unroll
    for (int i = 0; i < 2; i++) {
        const int idx = tid + i * 256;
        CP16(wdst + (uint32_t)idx * 16, wsrc + (size_t)idx * 16);
    }
}

__global__ __launch_bounds__(256, 3)
void iconv_mma_kernel(const int* __restrict__ neigh,
                      const float* __restrict__ bias,
                      float* __restrict__ out) {
    const uint32_t sb = smem_u32(smem_raw);
    const int tid  = threadIdx.x;
    const int lane = tid & 31;
    const int wid  = tid >> 5;
    const int b    = blockIdx.y;
    const int n0   = blockIdx.x * VT;
    const int vmax = min(VT, NV - n0);

    // stage bias + neighbor indices
    if (tid < C_) ((float*)(smem_raw + SOFF_BIAS))[tid] = bias[tid];
    {
        int* sN = (int*)(smem_raw + SOFF_NEIGH);
        const int lim = vmax * K_;
        #pragma unroll
        for (int i = 0; i < 4; i++) {
            const int q = tid + i * 256;
            if (q < VT * K_) sN[q] = (q < lim) ? neigh[(size_t)n0 * K_ + q] : 0;
        }
    }
    __syncthreads();

    const int* sN = (const int*)(smem_raw + SOFF_NEIGH);
    const __half* xhb = g_xh + (size_t)b * NV * C_;

    // warp tiling: 4 v-groups x 2 o-groups
    const int vg = wid >> 1;                  // vertices [vg*32, +32)
    const int og = wid & 1;                   // outputs  [og*32, +32)

    const int rowA = vg * 32 + (lane & 15);               // + i*16
    const uint32_t halfA = (uint32_t)((lane >> 4) * 16);
    const int rowB = (lane & 7) + ((lane >> 4) << 3);     // + og*32 + jp*16
    const uint32_t halfB = (uint32_t)(((lane >> 3) & 1) * 16);

    float acc[2][4][4];
    #pragma unroll
    for (int i = 0; i < 2; i++)
        #pragma unroll
        for (int j = 0; j < 4; j++)
            #pragma unroll
            for (int r = 0; r < 4; r++) acc[i][j][r] = 0.0f;

    stage_load(0, 0, vmax, sN, xhb, sb, tid);
    CP_COMMIT();

    for (int k = 0; k < K_; k++) {
        const int p = k & 1;
        if (k < K_ - 1) {
            stage_load(p ^ 1, k + 1, vmax, sN, xhb, sb, tid);
            CP_COMMIT();
            CP_WAIT1();
        } else {
            CP_WAIT0();
        }
        __syncthreads();

        const uint32_t aB = sb + SOFF_A(p);
        const uint32_t wB = sb + SOFF_W(p);

        #pragma unroll
        for (int kk = 0; kk < 4; kk++) {
            uint32_t aF[2][4];
            #pragma unroll
            for (int i = 0; i < 2; i++) {
                // half-offset added BEFORE the swizzle (no-carry there)
                const uint32_t offA =
                    SWZ((uint32_t)((rowA + i * 16) * 128 + kk * 32) + halfA);
                LDM_X4(aF[i][0], aF[i][1], aF[i][2], aF[i][3], aB + offA);
            }
            uint32_t bF[4][2];
            #pragma unroll
            for (int jp = 0; jp < 2; jp++) {
                const uint32_t offB =
                    SWZ((uint32_t)((og * 32 + jp * 16 + rowB) * 128 + kk * 32) + halfB);
                uint32_t r0, r1, r2, r3;
                LDM_X4(r0, r1, r2, r3, wB + offB);
                bF[2 * jp][0]     = r0;  bF[2 * jp][1]     = r1;
                bF[2 * jp + 1][0] = r2;  bF[2 * jp + 1][1] = r3;
            }
            #pragma unroll
            for (int i = 0; i < 2; i++)
                #pragma unroll
                for (int j = 0; j < 4; j++)
                    MMA16816F(acc[i][j], aF[i], bF[j]);
        }
        __syncthreads();   // done reading buf p before it is overwritten
    }

    // ---- epilogue: regs -> smem stage [v*65 + o] -> coalesced stores ----
    {
        float* st = (float*)smem_raw;      // 128*65*4 = 33,280 B (reuses stages)
        const int gid = lane >> 2;
        const int tg  = lane & 3;
        #pragma unroll
        for (int i = 0; i < 2; i++)
            #pragma unroll
            for (int j = 0; j < 4; j++)
                #pragma unroll
                for (int r = 0; r < 4; r++) {
                    const int v = vg * 32 + i * 16 + gid + (r >> 1) * 8;
                    const int o = og * 32 + j * 8 + 2 * tg + (r & 1);
                    st[v * 65 + o] = acc[i][j][r];
                }
        __syncthreads();

        const float* sBias = (const float*)(smem_raw + SOFF_BIAS);
        const int v  = tid & 127;          // 128 consecutive v -> full coalescing
        const int oh = (tid >> 7) * 32;    // output half
        if (v < vmax) {
            #pragma unroll
            for (int oo = 0; oo < 32; oo++) {
                const int o = oh + oo;
                out[((size_t)b * C_ + o) * NV + n0 + v] = st[v * 65 + o] + sBias[o];
            }
        }
    }
}

// ---------------------------------------------------------------------------
// Launch
// ---------------------------------------------------------------------------
extern "C" void kernel_launch(void* const* d_in, const int* in_sizes, int n_in,
                              void* d_out, int out_size) {
    const float* x     = (const float*)d_in[0];
    const int*   neigh = (const int*)d_in[1];    // JAX x64 disabled -> int32
    const float* W     = (const float*)d_in[2];
    const float* bias  = (const float*)d_in[3];
    float*       out   = (float*)d_out;

    cudaFuncSetAttribute(iconv_mma_kernel,
                         cudaFuncAttributeMaxDynamicSharedMemorySize, SMEM_TOTAL);

    dim3 tgrid((NV + 31) / 32, C_ / 32, B_);
    xprep_kernel<<<tgrid, dim3(32, 8)>>>(x);

    wprep_kernel<<<(K_ * C_ * C_ + 255) / 256, 256>>>(W);

    dim3 mgrid((NV + VT - 1) / VT, B_);          // (321, 8)
    iconv_mma_kernel<<<mgrid, 256, SMEM_TOTAL>>>(neigh, bias, out);
}